// round 2
// baseline (speedup 1.0000x reference)
#include <cuda_runtime.h>
#include <cstdint>
#include <cstddef>

// Problem constants
#define NC    4      // NUM_CAPS
#define CC    64     // IN_CAPS
#define DC    192    // DIM_CAPS
#define DPAD  196    // padded row stride in smem (4*odd -> conflict-free float4)
#define QQ    512    // N_CLASS * K_SAMPLES
#define ND    (NC*DC)   // 768
#define IDIM  768    // IN_DIM
#define EPSF  1e-8f

// Scratch (static device globals: allocation-free)
__device__ float g_hatm[NC*CC*DC];      // [n][c][d]
__device__ float g_hq[QQ*ND];           // [q][n*192+d]

// ---------------- packed fp32x2 helpers (sm_103a FFMA2 pipe) ----------------
__device__ __forceinline__ unsigned long long f2pack(float lo, float hi) {
    unsigned long long r;
    asm("mov.b64 %0, {%1, %2};" : "=l"(r) : "f"(lo), "f"(hi));
    return r;
}
__device__ __forceinline__ void f2unpack(unsigned long long v, float& lo, float& hi) {
    asm("mov.b64 {%0, %1}, %2;" : "=f"(lo), "=f"(hi) : "l"(v));
}
__device__ __forceinline__ unsigned long long ffma2(unsigned long long a,
                                                    unsigned long long b,
                                                    unsigned long long c) {
    unsigned long long d;
    asm("fma.rn.f32x2 %0, %1, %2, %3;" : "=l"(d) : "l"(a), "l"(b), "l"(c));
    return d;
}

// =============================================================================
// Kernel 1: fused GEMM  C[576 x 768] = [m;q] @ Wl^T
//   rows 0..63   -> hatm[n][c][d] = dot + b            (c = row)
//   rows 64..575 -> hq[q][n*192+d] = dot               (q = row-64)
// Wl row j (j = n*192+d) lives at W[(n*64+0)*192+d][:], exploiting the
// broadcast of W across in_caps.
// BM=64, BN=64, KT=32, 256 threads, 4x4 microtile via FFMA2 (cols paired).
// =============================================================================
#define GBM 64
#define GBN 64
#define GKT 32

__global__ __launch_bounds__(256, 1)
void gemm_kernel(const float* __restrict__ Am, const float* __restrict__ Aq,
                 const float* __restrict__ W,  const float* __restrict__ Bb)
{
    __shared__ __align__(16) float As[GBM][36];      // padded: conflict-free
    __shared__ __align__(16) float Bs[GKT][GBN + 4]; // stride 68 floats

    const int t   = threadIdx.x;
    const int tx  = t & 15;          // 16 col-groups of 4
    const int ty  = t >> 4;          // 16 row-groups of 4
    const int row0 = blockIdx.y * GBM;
    const int col0 = blockIdx.x * GBN;

    // A loader: 2 float4 per thread (rows la_r, la_r+32)
    const int la_r = t >> 3;             // 0..31
    const int la_c = (t & 7) << 2;       // 0,4,...,28
    const int r0g = row0 + la_r;
    const int r1g = row0 + la_r + 32;
    const float* arow0 = (r0g < 64) ? (Am + (size_t)r0g * IDIM)
                                    : (Aq + (size_t)(r0g - 64) * IDIM);
    const float* arow1 = (r1g < 64) ? (Am + (size_t)r1g * IDIM)
                                    : (Aq + (size_t)(r1g - 64) * IDIM);

    // B loader: 4 consecutive threads cover 32 consecutive k of one W row
    const int lb_j = t >> 2;             // 0..63
    const int lb_k = (t & 3) << 2;       // 0,4,8,12 (second ld at +16)
    const int gj = col0 + lb_j;
    const int bn = gj / DC;
    const int bd = gj - bn * DC;
    const float* brow = W + ((size_t)bn * CC * DC + bd) * IDIM;

    unsigned long long acc[4][2];
#pragma unroll
    for (int i = 0; i < 4; i++) { acc[i][0] = 0ull; acc[i][1] = 0ull; }

    for (int kt = 0; kt < IDIM; kt += GKT) {
        *(float4*)&As[la_r][la_c]      = *(const float4*)(arow0 + kt + la_c);
        *(float4*)&As[la_r + 32][la_c] = *(const float4*)(arow1 + kt + la_c);
        float4 b0 = *(const float4*)(brow + kt + lb_k);
        float4 b1 = *(const float4*)(brow + kt + lb_k + 16);
        Bs[lb_k + 0][lb_j] = b0.x;  Bs[lb_k + 1][lb_j] = b0.y;
        Bs[lb_k + 2][lb_j] = b0.z;  Bs[lb_k + 3][lb_j] = b0.w;
        Bs[lb_k + 16][lb_j] = b1.x; Bs[lb_k + 17][lb_j] = b1.y;
        Bs[lb_k + 18][lb_j] = b1.z; Bs[lb_k + 19][lb_j] = b1.w;
        __syncthreads();
#pragma unroll 8
        for (int k = 0; k < GKT; k++) {
            ulonglong2 bp = *(const ulonglong2*)&Bs[k][tx << 2];
#pragma unroll
            for (int i = 0; i < 4; i++) {
                float a = As[(ty << 2) + i][k];
                unsigned long long ad = f2pack(a, a);
                acc[i][0] = ffma2(ad, bp.x, acc[i][0]);
                acc[i][1] = ffma2(ad, bp.y, acc[i][1]);
            }
        }
        __syncthreads();
    }

    const int jb = col0 + (tx << 2);
#pragma unroll
    for (int i = 0; i < 4; i++) {
        const int r = row0 + (ty << 2) + i;
        float v0, v1, v2, v3;
        f2unpack(acc[i][0], v0, v1);
        f2unpack(acc[i][1], v2, v3);
        if (r < 64) {
            float vv[4] = {v0, v1, v2, v3};
#pragma unroll
            for (int cj = 0; cj < 4; cj++) {
                const int j = jb + cj;
                const int n = j / DC;
                const int d = j - n * DC;
                const int idx = (n * CC + r) * DC + d;
                g_hatm[idx] = vv[cj] + Bb[idx];
            }
        } else {
            float4 o; o.x = v0; o.y = v1; o.z = v2; o.w = v3;
            *(float4*)(g_hq + (size_t)(r - 64) * ND + jb) = o;
        }
    }
}

// =============================================================================
// Kernel 2: per-query routing. One CTA per SM; tm (hatm) resident in smem.
// 256 threads: thread t owns pair (n,c) = (t>>6, t&63).
// =============================================================================

__device__ __forceinline__ void tq_stats(const float* __restrict__ s_tq,
                                         float* __restrict__ s_stat,
                                         int warp, int lane)
{
    if (warp < 4) {
        const float* tqn = s_tq + warp * DC;
        float s = 0.f;
#pragma unroll
        for (int d = lane; d < DC; d += 32) s += tqn[d];
#pragma unroll
        for (int o = 16; o > 0; o >>= 1) s += __shfl_xor_sync(0xffffffffu, s, o);
        const float muq = s * (1.0f / DC);
        float ss = 0.f;
#pragma unroll
        for (int d = lane; d < DC; d += 32) { float x = tqn[d] - muq; ss += x * x; }
#pragma unroll
        for (int o = 16; o > 0; o >>= 1) ss += __shfl_xor_sync(0xffffffffu, ss, o);
        if (lane == 0) { s_stat[warp] = s; s_stat[4 + warp] = ss; }
    }
}

__global__ __launch_bounds__(256, 1)
void routing_kernel(float* __restrict__ out)
{
    extern __shared__ float sm[];
    float* s_tm   = sm;                        // [256][196]
    float* s_mu   = sm + 256 * DPAD;           // 256
    float* s_sxx  = s_mu + 256;                // 256
    float* s_a    = s_sxx + 256;               // 256
    float* s_p    = s_a + 256;                 // 256
    float* s_co   = s_p + 256;                 // 256
    float* s_tq   = s_co + 256;                // 768
    float* s_hv   = s_tq + ND;                 // 768
    float* s_stat = s_hv + ND;                 // 16: S1[0..3], syy[4..7], scale[8..11]

    const int t = threadIdx.x;
    const int warp = t >> 5, lane = t & 31;
    const int n_own = t >> 6;
    const float* rowp = s_tm + t * DPAD;

    // Load tm into smem (padded rows)
    for (int idx = t; idx < NC * CC * DC; idx += 256) {
        const int row = idx / DC;
        const int d = idx - row * DC;
        s_tm[row * DPAD + d] = g_hatm[idx];
    }
    __syncthreads();

    // Per-(n,c) mean / centered sum-of-squares (constants across q)
    {
        float s = 0.f;
#pragma unroll 8
        for (int d = 0; d < DC; d += 4) {
            float4 v = *(const float4*)(rowp + d);
            s += (v.x + v.y) + (v.z + v.w);
        }
        const float mu = s * (1.0f / DC);
        float ss = 0.f;
#pragma unroll 8
        for (int d = 0; d < DC; d += 4) {
            float4 v = *(const float4*)(rowp + d);
            float e0 = v.x - mu, e1 = v.y - mu, e2 = v.z - mu, e3 = v.w - mu;
            ss += (e0 * e0 + e1 * e1) + (e2 * e2 + e3 * e3);
        }
        s_mu[t] = mu; s_sxx[t] = ss;
    }

    for (int q = blockIdx.x; q < QQ; q += gridDim.x) {
        __syncthreads();
        for (int idx = t; idx < ND; idx += 256) s_tq[idx] = g_hq[(size_t)q * ND + idx];
        s_a[t] = 0.f;
        __syncthreads();

        tq_stats(s_tq, s_stat, warp, lane);
        __syncthreads();

        // initial p = tanh(-pearson(tm, tq)); num = dot(tm,tq) - mu*S1
        {
            const float* tqn = s_tq + n_own * DC;
            float a0 = 0.f, a1 = 0.f, a2 = 0.f, a3 = 0.f;
#pragma unroll 8
            for (int d = 0; d < DC; d += 4) {
                float4 x = *(const float4*)(rowp + d);
                float4 y = *(const float4*)(tqn + d);
                a0 += x.x * y.x; a1 += x.y * y.y; a2 += x.z * y.z; a3 += x.w * y.w;
            }
            const float dot = (a0 + a1) + (a2 + a3);
            const float num = dot - s_mu[t] * s_stat[n_own];
            s_p[t] = tanhf(-num / sqrtf(s_sxx[t] * s_stat[4 + n_own] + EPSF));
        }
        __syncthreads();

#pragma unroll
        for (int it = 0; it < 3; it++) {
            // softmax over n (per c), coeff = d + p
            if (t < CC) {
                float a0 = s_a[t], a1 = s_a[CC + t], a2 = s_a[2 * CC + t], a3 = s_a[3 * CC + t];
                float mx = fmaxf(fmaxf(a0, a1), fmaxf(a2, a3));
                float e0 = expf(a0 - mx), e1 = expf(a1 - mx), e2 = expf(a2 - mx), e3 = expf(a3 - mx);
                float inv = 1.0f / (e0 + e1 + e2 + e3);
                s_co[t]          = e0 * inv + s_p[t];
                s_co[CC + t]     = e1 * inv + s_p[CC + t];
                s_co[2 * CC + t] = e2 * inv + s_p[2 * CC + t];
                s_co[3 * CC + t] = e3 * inv + s_p[3 * CC + t];
            }
            __syncthreads();

            // hat_v[n,d] = sum_c coeff[n,c] * tm[n,c,d]
            if (t < 192) {
                const int n = t / 48;
                const int d4 = (t - n * 48) << 2;
                const float* base = s_tm + (n * CC) * DPAD + d4;
                const float* cof = s_co + n * CC;
                float ax = 0.f, ay = 0.f, az = 0.f, aw = 0.f;
#pragma unroll 8
                for (int c = 0; c < CC; c++) {
                    const float w = cof[c];
                    float4 v = *(const float4*)(base + c * DPAD);
                    ax += w * v.x; ay += w * v.y; az += w * v.z; aw += w * v.w;
                }
                float4 o; o.x = ax; o.y = ay; o.z = az; o.w = aw;
                *(float4*)(s_hv + n * DC + d4) = o;
            }
            __syncthreads();

            // squash scale per n
            if (warp < 4) {
                const float* hvn = s_hv + warp * DC;
                float s = 0.f;
#pragma unroll
                for (int d = lane; d < DC; d += 32) { float x = hvn[d]; s += x * x; }
#pragma unroll
                for (int o = 16; o > 0; o >>= 1) s += __shfl_xor_sync(0xffffffffu, s, o);
                if (lane == 0) s_stat[8 + warp] = (s / (1.0f + s)) / sqrtf(s + EPSF);
            }
            __syncthreads();

            if (it == 2) break;   // final round: only scaled hat_v -> output

            // v = hv*scale ; tq = (tq + v)*0.5
            for (int idx = t; idx < ND; idx += 256) {
                const int n = idx / DC;
                const float v = s_hv[idx] * s_stat[8 + n];
                s_hv[idx] = v;
                s_tq[idx] = (s_tq[idx] + v) * 0.5f;
            }
            __syncthreads();

            tq_stats(s_tq, s_stat, warp, lane);
            __syncthreads();

            // fused pass: agree = tm.v ; dotq = tm.tq' ; a += p*agree ; p = new pearson
            {
                const float* vv  = s_hv + n_own * DC;
                const float* tqn = s_tq + n_own * DC;
                float g0 = 0.f, g1 = 0.f, g2 = 0.f, g3 = 0.f;
                float h0 = 0.f, h1 = 0.f, h2 = 0.f, h3 = 0.f;
#pragma unroll 4
                for (int d = 0; d < DC; d += 4) {
                    float4 x  = *(const float4*)(rowp + d);
                    float4 a4 = *(const float4*)(vv + d);
                    float4 b4 = *(const float4*)(tqn + d);
                    g0 += x.x * a4.x; g1 += x.y * a4.y; g2 += x.z * a4.z; g3 += x.w * a4.w;
                    h0 += x.x * b4.x; h1 += x.y * b4.y; h2 += x.z * b4.z; h3 += x.w * b4.w;
                }
                const float agree = (g0 + g1) + (g2 + g3);
                const float dotq  = (h0 + h1) + (h2 + h3);
                s_a[t] += s_p[t] * agree;
                const float num = dotq - s_mu[t] * s_stat[n_own];
                s_p[t] = tanhf(-num / sqrtf(s_sxx[t] * s_stat[4 + n_own] + EPSF));
            }
            __syncthreads();
        }

        // v_out = hv * scale  -> out[q, n*192+d]
        for (int idx = t; idx < ND; idx += 256) {
            const int n = idx / DC;
            out[(size_t)q * ND + idx] = s_hv[idx] * s_stat[8 + n];
        }
    }
}

// =============================================================================
// launch
// =============================================================================
extern "C" void kernel_launch(void* const* d_in, const int* in_sizes, int n_in,
                              void* d_out, int out_size)
{
    const float* m = (const float*)d_in[0];   // [64, 768]
    const float* q = (const float*)d_in[1];   // [512, 768]
    const float* W = (const float*)d_in[2];   // [1, 4, 64, 192, 768]
    const float* b = (const float*)d_in[3];   // [1, 4, 64, 192]
    float* out = (float*)d_out;               // [512, 768]
    (void)in_sizes; (void)n_in; (void)out_size;

    const size_t smem_bytes =
        (size_t)(256 * DPAD + 256 * 5 + 2 * ND + 16) * sizeof(float); // ~212 KB
    cudaFuncSetAttribute(routing_kernel,
                         cudaFuncAttributeMaxDynamicSharedMemorySize,
                         (int)smem_bytes);

    gemm_kernel<<<dim3(12, 9), 256>>>(m, q, W, b);
    routing_kernel<<<148, 256, smem_bytes>>>(out);
}

// round 3
// speedup vs baseline: 1.0475x; 1.0475x over previous
#include <cuda_runtime.h>
#include <cstdint>
#include <cstddef>

// Problem constants
#define NC    4      // NUM_CAPS
#define CC    64     // IN_CAPS
#define DC    192    // DIM_CAPS
#define DPAD  196    // padded row stride in smem
#define QQ    512
#define ND    (NC*DC)   // 768
#define IDIM  768
#define EPSF  1e-8f
#define PQ    2336   // per-query smem block: a(256)+p(256)+co(256)+tq(768)+hv(768)+stat(32)

__device__ float g_hatm[NC*CC*DC];      // [n][c][d]
__device__ float g_hq[QQ*ND];           // [q][n*192+d]

// ---------------- packed fp32x2 helpers ----------------
__device__ __forceinline__ void f2unpack(unsigned long long v, float& lo, float& hi) {
    asm("mov.b64 {%0, %1}, %2;" : "=f"(lo), "=f"(hi) : "l"(v));
}
__device__ __forceinline__ unsigned long long ffma2(unsigned long long a,
                                                    unsigned long long b,
                                                    unsigned long long c) {
    unsigned long long d;
    asm("fma.rn.f32x2 %0, %1, %2, %3;" : "=l"(d) : "l"(a), "l"(b), "l"(c));
    return d;
}

// =============================================================================
// Kernel 1: fused GEMM  C[576 x 768] = [m;q] @ Wl^T  (FFMA2 pipe)
// As stored duplicated as float2(a,a) so the inner loop has no pack movs.
// =============================================================================
#define GBM 64
#define GBN 64
#define GKT 32

__global__ __launch_bounds__(256, 1)
void gemm_kernel(const float* __restrict__ Am, const float* __restrict__ Aq,
                 const float* __restrict__ W,  const float* __restrict__ Bb)
{
    __shared__ __align__(16) float2 As2[GBM][GKT + 2];   // dup'd A, stride 34 f2
    __shared__ __align__(16) float  Bs[GKT][GBN + 4];

    const int t   = threadIdx.x;
    const int tx  = t & 15;
    const int ty  = t >> 4;
    const int row0 = blockIdx.y * GBM;
    const int col0 = blockIdx.x * GBN;

    const int la_r = t >> 3;
    const int la_c = (t & 7) << 2;
    const int r0g = row0 + la_r;
    const int r1g = row0 + la_r + 32;
    const float* arow0 = (r0g < 64) ? (Am + (size_t)r0g * IDIM)
                                    : (Aq + (size_t)(r0g - 64) * IDIM);
    const float* arow1 = (r1g < 64) ? (Am + (size_t)r1g * IDIM)
                                    : (Aq + (size_t)(r1g - 64) * IDIM);

    const int lb_j = t >> 2;
    const int lb_k = (t & 3) << 2;
    const int gj = col0 + lb_j;
    const int bn = gj / DC;
    const int bd = gj - bn * DC;
    const float* brow = W + ((size_t)bn * CC * DC + bd) * IDIM;

    unsigned long long acc[4][2];
#pragma unroll
    for (int i = 0; i < 4; i++) { acc[i][0] = 0ull; acc[i][1] = 0ull; }

    for (int kt = 0; kt < IDIM; kt += GKT) {
        float4 a0 = *(const float4*)(arow0 + kt + la_c);
        float4 a1 = *(const float4*)(arow1 + kt + la_c);
        As2[la_r][la_c + 0] = make_float2(a0.x, a0.x);
        As2[la_r][la_c + 1] = make_float2(a0.y, a0.y);
        As2[la_r][la_c + 2] = make_float2(a0.z, a0.z);
        As2[la_r][la_c + 3] = make_float2(a0.w, a0.w);
        As2[la_r + 32][la_c + 0] = make_float2(a1.x, a1.x);
        As2[la_r + 32][la_c + 1] = make_float2(a1.y, a1.y);
        As2[la_r + 32][la_c + 2] = make_float2(a1.z, a1.z);
        As2[la_r + 32][la_c + 3] = make_float2(a1.w, a1.w);
        float4 b0 = *(const float4*)(brow + kt + lb_k);
        float4 b1 = *(const float4*)(brow + kt + lb_k + 16);
        Bs[lb_k + 0][lb_j] = b0.x;  Bs[lb_k + 1][lb_j] = b0.y;
        Bs[lb_k + 2][lb_j] = b0.z;  Bs[lb_k + 3][lb_j] = b0.w;
        Bs[lb_k + 16][lb_j] = b1.x; Bs[lb_k + 17][lb_j] = b1.y;
        Bs[lb_k + 18][lb_j] = b1.z; Bs[lb_k + 19][lb_j] = b1.w;
        __syncthreads();
#pragma unroll 8
        for (int k = 0; k < GKT; k++) {
            ulonglong2 bp = *(const ulonglong2*)&Bs[k][tx << 2];
            unsigned long long ad0 = *(const unsigned long long*)&As2[(ty << 2) + 0][k];
            unsigned long long ad1 = *(const unsigned long long*)&As2[(ty << 2) + 1][k];
            unsigned long long ad2 = *(const unsigned long long*)&As2[(ty << 2) + 2][k];
            unsigned long long ad3 = *(const unsigned long long*)&As2[(ty << 2) + 3][k];
            acc[0][0] = ffma2(ad0, bp.x, acc[0][0]);
            acc[0][1] = ffma2(ad0, bp.y, acc[0][1]);
            acc[1][0] = ffma2(ad1, bp.x, acc[1][0]);
            acc[1][1] = ffma2(ad1, bp.y, acc[1][1]);
            acc[2][0] = ffma2(ad2, bp.x, acc[2][0]);
            acc[2][1] = ffma2(ad2, bp.y, acc[2][1]);
            acc[3][0] = ffma2(ad3, bp.x, acc[3][0]);
            acc[3][1] = ffma2(ad3, bp.y, acc[3][1]);
        }
        __syncthreads();
    }

    const int jb = col0 + (tx << 2);
#pragma unroll
    for (int i = 0; i < 4; i++) {
        const int r = row0 + (ty << 2) + i;
        float v0, v1, v2, v3;
        f2unpack(acc[i][0], v0, v1);
        f2unpack(acc[i][1], v2, v3);
        if (r < 64) {
            float vv[4] = {v0, v1, v2, v3};
#pragma unroll
            for (int cj = 0; cj < 4; cj++) {
                const int j = jb + cj;
                const int n = j / DC;
                const int d = j - n * DC;
                const int idx = (n * CC + r) * DC + d;
                g_hatm[idx] = vv[cj] + Bb[idx];
            }
        } else {
            float4 o; o.x = v0; o.y = v1; o.z = v2; o.w = v3;
            *(float4*)(g_hq + (size_t)(r - 64) * ND + jb) = o;
        }
    }
}

// =============================================================================
// Kernel 2: routing, 512 threads = two 256-thread halves (query pair).
// tm resident in smem (196 KB), shared by both halves.
// s_stat layout (per query): [0..7] partial S1 (2 per n), [8..15] partial ss,
//                            [16..19] squash scale per n.
// =============================================================================
__global__ __launch_bounds__(512, 1)
void routing_kernel(float* __restrict__ out)
{
    extern __shared__ float sm[];
    float* s_tm  = sm;                         // [256][196]
    float* s_mu  = sm + 256 * DPAD;            // 256 (query-independent)
    float* s_sxx = s_mu + 256;                 // 256
    float* qbase = s_sxx + 256;                // 2 x PQ

    const int t    = threadIdx.x;
    const int qi   = t >> 8;                   // query-in-pair
    const int tl   = t & 255;                  // thread-in-half
    const int warp = t >> 5;
    const int lane = t & 31;
    const int wl   = warp & 7;                 // warp-in-half
    const int n_own = tl >> 6;

    float* qb     = qbase + qi * PQ;
    float* s_a    = qb;
    float* s_p    = qb + 256;
    float* s_co   = qb + 512;
    float* s_tq   = qb + 768;
    float* s_hv   = qb + 1536;
    float* s_stat = qb + 2304;
    float* co_q0  = qbase + 512;
    float* co_q1  = qbase + PQ + 512;
    float* hv_q0  = qbase + 1536;
    float* hv_q1  = qbase + PQ + 1536;

    const float* rowp = s_tm + tl * DPAD;

    // Load tm (512 threads)
    for (int idx = t; idx < NC * CC * DC; idx += 512) {
        const int row = idx / DC;
        const int d = idx - row * DC;
        s_tm[row * DPAD + d] = g_hatm[idx];
    }
    __syncthreads();

    // Per-(n,c) tm stats (query-independent) — first half only
    if (qi == 0) {
        float s = 0.f;
#pragma unroll 8
        for (int d = 0; d < DC; d += 4) {
            float4 v = *(const float4*)(rowp + d);
            s += (v.x + v.y) + (v.z + v.w);
        }
        const float mu = s * (1.0f / DC);
        float ss = 0.f;
#pragma unroll 8
        for (int d = 0; d < DC; d += 4) {
            float4 v = *(const float4*)(rowp + d);
            float e0 = v.x - mu, e1 = v.y - mu, e2 = v.z - mu, e3 = v.w - mu;
            ss += (e0 * e0 + e1 * e1) + (e2 * e2 + e3 * e3);
        }
        s_mu[tl] = mu; s_sxx[tl] = ss;
    }

    for (int pp = blockIdx.x; pp < QQ / 2; pp += gridDim.x) {
        const int q = 2 * pp + qi;
        __syncthreads();   // protect buffers from previous pair / tm-stat phase

        for (int idx = tl; idx < ND; idx += 256)
            s_tq[idx] = g_hq[(size_t)q * ND + idx];
        s_a[tl] = 0.f;
        __syncthreads();

        // initial tq stats: one warp per n per half, single pass (uncentered)
        if (wl < 4) {
            const float* tqn = s_tq + wl * DC;
            float s = 0.f, ss = 0.f;
#pragma unroll
            for (int d = lane; d < DC; d += 32) { float x = tqn[d]; s += x; ss += x * x; }
#pragma unroll
            for (int o = 16; o > 0; o >>= 1) {
                s  += __shfl_xor_sync(0xffffffffu, s, o);
                ss += __shfl_xor_sync(0xffffffffu, ss, o);
            }
            if (lane == 0) { s_stat[2 * wl] = s;  s_stat[8 + 2 * wl] = ss; }
            if (lane == 1) { s_stat[2 * wl + 1] = 0.f; s_stat[8 + 2 * wl + 1] = 0.f; }
        }
        __syncthreads();

        // initial p = tanh(-pearson(tm, tq))
        {
            const float* tqn = s_tq + n_own * DC;
            float a0 = 0.f, a1 = 0.f, a2 = 0.f, a3 = 0.f;
#pragma unroll 8
            for (int d = 0; d < DC; d += 4) {
                float4 x = *(const float4*)(rowp + d);
                float4 y = *(const float4*)(tqn + d);
                a0 += x.x * y.x; a1 += x.y * y.y; a2 += x.z * y.z; a3 += x.w * y.w;
            }
            const float dot = (a0 + a1) + (a2 + a3);
            const float S1  = s_stat[2 * n_own] + s_stat[2 * n_own + 1];
            const float ssr = s_stat[8 + 2 * n_own] + s_stat[8 + 2 * n_own + 1];
            const float syy = ssr - S1 * S1 * (1.0f / DC);
            const float num = dot - s_mu[tl] * S1;
            s_p[tl] = tanhf(-num / sqrtf(s_sxx[tl] * syy + EPSF));
        }
        __syncthreads();

#pragma unroll
        for (int it = 0; it < 3; it++) {
            // softmax over n (per c), coeff = d + p  (both halves, tl<64)
            if (tl < CC) {
                float a0 = s_a[tl], a1 = s_a[CC + tl], a2 = s_a[2 * CC + tl], a3 = s_a[3 * CC + tl];
                float mx = fmaxf(fmaxf(a0, a1), fmaxf(a2, a3));
                float e0 = expf(a0 - mx), e1 = expf(a1 - mx), e2 = expf(a2 - mx), e3 = expf(a3 - mx);
                float inv = 1.0f / (e0 + e1 + e2 + e3);
                s_co[tl]          = e0 * inv + s_p[tl];
                s_co[CC + tl]     = e1 * inv + s_p[CC + tl];
                s_co[2 * CC + tl] = e2 * inv + s_p[2 * CC + tl];
                s_co[3 * CC + tl] = e3 * inv + s_p[3 * CC + tl];
            }
            __syncthreads();

            // hat_v for BOTH queries with one tm read (t < 384, float2 granularity)
            if (t < 384) {
                const int n  = t / 96;
                const int d  = (t - n * 96) << 1;
                const float* basep = s_tm + (n * CC) * DPAD + d;
                const float* c0 = co_q0 + n * CC;
                const float* c1 = co_q1 + n * CC;
                float ax0 = 0.f, ay0 = 0.f, ax1 = 0.f, ay1 = 0.f;
#pragma unroll 8
                for (int c = 0; c < CC; c++) {
                    float2 v = *(const float2*)(basep + c * DPAD);
                    const float w0 = c0[c], w1 = c1[c];
                    ax0 += w0 * v.x; ay0 += w0 * v.y;
                    ax1 += w1 * v.x; ay1 += w1 * v.y;
                }
                *(float2*)(hv_q0 + n * DC + d) = make_float2(ax0, ay0);
                *(float2*)(hv_q1 + n * DC + d) = make_float2(ax1, ay1);
            }
            __syncthreads();

            // squash scale per n (one warp per n per half)
            if (wl < 4) {
                const float* hvn = s_hv + wl * DC;
                float s = 0.f;
#pragma unroll
                for (int d = lane; d < DC; d += 32) { float x = hvn[d]; s += x * x; }
#pragma unroll
                for (int o = 16; o > 0; o >>= 1) s += __shfl_xor_sync(0xffffffffu, s, o);
                if (lane == 0) s_stat[16 + wl] = (s / (1.0f + s)) / sqrtf(s + EPSF);
            }
            __syncthreads();

            if (it == 2) break;

            // update: v = hv*scale ; tq = (tq+v)*0.5 ; fused partial tq stats
            {
                const int n = wl >> 1, seg = wl & 1;
                const int off0 = n * DC + seg * 96;
                const float scale = s_stat[16 + n];
                float s = 0.f, ss = 0.f;
#pragma unroll
                for (int k = 0; k < 3; k++) {
                    const int off = off0 + k * 32 + lane;
                    const float v = s_hv[off] * scale;
                    s_hv[off] = v;
                    const float nt = (s_tq[off] + v) * 0.5f;
                    s_tq[off] = nt;
                    s += nt; ss += nt * nt;
                }
#pragma unroll
                for (int o = 16; o > 0; o >>= 1) {
                    s  += __shfl_xor_sync(0xffffffffu, s, o);
                    ss += __shfl_xor_sync(0xffffffffu, ss, o);
                }
                if (lane == 0) { s_stat[wl] = s; s_stat[8 + wl] = ss; }
            }
            __syncthreads();

            // fused: agree = tm.v ; dotq = tm.tq ; a += p*agree ; new p
            {
                const float* vv  = s_hv + n_own * DC;
                const float* tqn = s_tq + n_own * DC;
                float g0 = 0.f, g1 = 0.f, g2 = 0.f, g3 = 0.f;
                float h0 = 0.f, h1 = 0.f, h2 = 0.f, h3 = 0.f;
#pragma unroll 4
                for (int d = 0; d < DC; d += 4) {
                    float4 x  = *(const float4*)(rowp + d);
                    float4 a4 = *(const float4*)(vv + d);
                    float4 b4 = *(const float4*)(tqn + d);
                    g0 += x.x * a4.x; g1 += x.y * a4.y; g2 += x.z * a4.z; g3 += x.w * a4.w;
                    h0 += x.x * b4.x; h1 += x.y * b4.y; h2 += x.z * b4.z; h3 += x.w * b4.w;
                }
                const float agree = (g0 + g1) + (g2 + g3);
                const float dotq  = (h0 + h1) + (h2 + h3);
                s_a[tl] += s_p[tl] * agree;
                const float S1  = s_stat[2 * n_own] + s_stat[2 * n_own + 1];
                const float ssr = s_stat[8 + 2 * n_own] + s_stat[8 + 2 * n_own + 1];
                const float syy = ssr - S1 * S1 * (1.0f / DC);
                const float num = dotq - s_mu[tl] * S1;
                s_p[tl] = tanhf(-num / sqrtf(s_sxx[tl] * syy + EPSF));
            }
            __syncthreads();
        }

        // v_out = hv * scale
        for (int idx = tl; idx < ND; idx += 256) {
            const int n = idx / DC;
            out[(size_t)q * ND + idx] = s_hv[idx] * s_stat[16 + n];
        }
    }
}

// =============================================================================
// launch
// =============================================================================
extern "C" void kernel_launch(void* const* d_in, const int* in_sizes, int n_in,
                              void* d_out, int out_size)
{
    const float* m = (const float*)d_in[0];   // [64, 768]
    const float* q = (const float*)d_in[1];   // [512, 768]
    const float* W = (const float*)d_in[2];   // [1, 4, 64, 192, 768]
    const float* b = (const float*)d_in[3];   // [1, 4, 64, 192]
    float* out = (float*)d_out;               // [512, 768]
    (void)in_sizes; (void)n_in; (void)out_size;

    const size_t smem_bytes =
        (size_t)(256 * DPAD + 512 + 2 * PQ) * sizeof(float); // ~216 KB
    cudaFuncSetAttribute(routing_kernel,
                         cudaFuncAttributeMaxDynamicSharedMemorySize,
                         (int)smem_bytes);

    gemm_kernel<<<dim3(12, 9), 256>>>(m, q, W, b);
    routing_kernel<<<148, 512, smem_bytes>>>(out);
}

// round 4
// speedup vs baseline: 1.2962x; 1.2374x over previous
#include <cuda_runtime.h>
#include <cstdint>
#include <cstddef>

// Problem constants
#define NC    4      // NUM_CAPS
#define CC    64     // IN_CAPS
#define DC    192    // DIM_CAPS
#define DPAD  196    // padded row stride in smem (float4-stride 49: conflict-free)
#define QQ    512
#define ND    (NC*DC)   // 768
#define IDIM  768
#define EPSF  1e-8f
#define PQ    2336   // per-query block: a(256)+p(256)+co(256)+tq(768)+hv(768)+stat(32)

__device__ float g_hatm[NC*CC*DC];      // [n][c][d]
__device__ float g_hq[QQ*ND];           // [q][n*192+d]

// ---------------- packed fp32x2 helpers (sm_103a FFMA2 pipe) ----------------
typedef unsigned long long u64;
__device__ __forceinline__ void f2unpack(u64 v, float& lo, float& hi) {
    asm("mov.b64 {%0, %1}, %2;" : "=f"(lo), "=f"(hi) : "l"(v));
}
__device__ __forceinline__ u64 f2dup(float a) {
    u64 r;
    asm("mov.b64 %0, {%1, %1};" : "=l"(r) : "f"(a));
    return r;
}
__device__ __forceinline__ u64 ffma2(u64 a, u64 b, u64 c) {
    u64 d;
    asm("fma.rn.f32x2 %0, %1, %2, %3;" : "=l"(d) : "l"(a), "l"(b), "l"(c));
    return d;
}

// =============================================================================
// Kernel 1: fused GEMM  C[576 x 768] = [m;q] @ Wl^T  (FFMA2)
// BM=48, BN=64, KT=64 -> grid (12,12) = 144 CTAs = one full wave.
// Scalar As (pad 68), dup in-register; 3x4 microtile per thread.
// =============================================================================
#define GBM 48
#define GBN 64
#define GKT 64
#define APAD 68

__global__ __launch_bounds__(256, 1)
void gemm_kernel(const float* __restrict__ Am, const float* __restrict__ Aq,
                 const float* __restrict__ W,  const float* __restrict__ Bb)
{
    __shared__ __align__(16) float As[GBM][APAD];      // 48*68*4 = 13056 B
    __shared__ __align__(16) float Bs[GKT][GBN + 4];   // 64*68*4 = 17408 B

    const int t   = threadIdx.x;
    const int tx  = t & 15;
    const int ty  = t >> 4;
    const int row0 = blockIdx.y * GBM;
    const int col0 = blockIdx.x * GBN;

    // A loader: 3 float4 per thread covering the 48x64 tile
    const float* aptr[3];
    int arow[3], acol[3];
#pragma unroll
    for (int j = 0; j < 3; j++) {
        const int i = t + 256 * j;           // 0..767
        arow[j] = i >> 4;                    // 0..47
        acol[j] = (i & 15) << 2;             // 0..60
        const int rg = row0 + arow[j];
        aptr[j] = ((rg < 64) ? (Am + (size_t)rg * IDIM)
                             : (Aq + (size_t)(rg - 64) * IDIM)) + acol[j];
    }

    // B loader: 4 float4 per thread (one W row segment of 64 k)
    const int lb_j = t >> 2;                 // 0..63
    const int lb_k = (t & 3) << 2;           // 0,4,8,12
    const int gj = col0 + lb_j;
    const int bn = gj / DC;
    const int bd = gj - bn * DC;
    const float* brow = W + ((size_t)bn * CC * DC + bd) * IDIM + lb_k;

    u64 acc[3][2];
#pragma unroll
    for (int i = 0; i < 3; i++) { acc[i][0] = 0ull; acc[i][1] = 0ull; }

    for (int kt = 0; kt < IDIM; kt += GKT) {
#pragma unroll
        for (int j = 0; j < 3; j++) {
            float4 a = *(const float4*)(aptr[j] + kt);
            *(float4*)&As[arow[j]][acol[j]] = a;
        }
#pragma unroll
        for (int c = 0; c < 4; c++) {
            float4 b = *(const float4*)(brow + kt + 16 * c);
            Bs[lb_k + 16 * c + 0][lb_j] = b.x;
            Bs[lb_k + 16 * c + 1][lb_j] = b.y;
            Bs[lb_k + 16 * c + 2][lb_j] = b.z;
            Bs[lb_k + 16 * c + 3][lb_j] = b.w;
        }
        __syncthreads();
#pragma unroll 16
        for (int k = 0; k < GKT; k++) {
            ulonglong2 bp = *(const ulonglong2*)&Bs[k][tx << 2];
            u64 a0 = f2dup(As[ty * 3 + 0][k]);
            u64 a1 = f2dup(As[ty * 3 + 1][k]);
            u64 a2 = f2dup(As[ty * 3 + 2][k]);
            acc[0][0] = ffma2(a0, bp.x, acc[0][0]);
            acc[0][1] = ffma2(a0, bp.y, acc[0][1]);
            acc[1][0] = ffma2(a1, bp.x, acc[1][0]);
            acc[1][1] = ffma2(a1, bp.y, acc[1][1]);
            acc[2][0] = ffma2(a2, bp.x, acc[2][0]);
            acc[2][1] = ffma2(a2, bp.y, acc[2][1]);
        }
        __syncthreads();
    }

    const int jb = col0 + (tx << 2);
#pragma unroll
    for (int i = 0; i < 3; i++) {
        const int r = row0 + ty * 3 + i;
        float v0, v1, v2, v3;
        f2unpack(acc[i][0], v0, v1);
        f2unpack(acc[i][1], v2, v3);
        if (r < 64) {
            float vv[4] = {v0, v1, v2, v3};
#pragma unroll
            for (int cj = 0; cj < 4; cj++) {
                const int j = jb + cj;
                const int n = j / DC;
                const int d = j - n * DC;
                const int idx = (n * CC + r) * DC + d;
                g_hatm[idx] = vv[cj] + Bb[idx];
            }
        } else {
            float4 o; o.x = v0; o.y = v1; o.z = v2; o.w = v3;
            *(float4*)(g_hq + (size_t)(r - 64) * ND + jb) = o;
        }
    }
}

// =============================================================================
// Kernel 2: routing, 512 threads = two 256-thread halves (query pair).
// tm resident in smem. FFMA2 dot loops; squash fused into hat_v.
// s_stat per query: [0..7] S1 partials (2/n), [8..15] ss partials,
//                   [16..27] ||hv||^2 warp partials (3/n).
// =============================================================================
__global__ __launch_bounds__(512, 1)
void routing_kernel(float* __restrict__ out)
{
    extern __shared__ float sm[];
    float* s_tm  = sm;                         // [256][196]
    float* s_mu  = sm + 256 * DPAD;            // 256 (query-independent)
    float* s_sxx = s_mu + 256;                 // 256
    float* qbase = s_sxx + 256;                // 2 x PQ

    const int t    = threadIdx.x;
    const int qi   = t >> 8;
    const int tl   = t & 255;
    const int warp = t >> 5;
    const int lane = t & 31;
    const int wl   = warp & 7;
    const int n_own = tl >> 6;

    float* qb     = qbase + qi * PQ;
    float* s_a    = qb;
    float* s_p    = qb + 256;
    float* s_co   = qb + 512;
    float* s_tq   = qb + 768;
    float* s_hv   = qb + 1536;
    float* s_stat = qb + 2304;
    float* co_q0  = qbase + 512;
    float* co_q1  = qbase + PQ + 512;
    float* hv_q0  = qbase + 1536;
    float* hv_q1  = qbase + PQ + 1536;
    float* st_q0  = qbase + 2304;
    float* st_q1  = qbase + PQ + 2304;

    const float* rowp = s_tm + tl * DPAD;

    // Load tm
    for (int idx = t; idx < NC * CC * DC; idx += 512) {
        const int row = idx / DC;
        const int d = idx - row * DC;
        s_tm[row * DPAD + d] = g_hatm[idx];
    }
    __syncthreads();

    // Per-(n,c) tm stats (query-independent)
    if (qi == 0) {
        float s = 0.f;
#pragma unroll 8
        for (int d = 0; d < DC; d += 4) {
            float4 v = *(const float4*)(rowp + d);
            s += (v.x + v.y) + (v.z + v.w);
        }
        const float mu = s * (1.0f / DC);
        float ss = 0.f;
#pragma unroll 8
        for (int d = 0; d < DC; d += 4) {
            float4 v = *(const float4*)(rowp + d);
            float e0 = v.x - mu, e1 = v.y - mu, e2 = v.z - mu, e3 = v.w - mu;
            ss += (e0 * e0 + e1 * e1) + (e2 * e2 + e3 * e3);
        }
        s_mu[tl] = mu; s_sxx[tl] = ss;
    }

    for (int pp = blockIdx.x; pp < QQ / 2; pp += gridDim.x) {
        const int q = 2 * pp + qi;
        __syncthreads();

        if (tl < 192)
            *(float4*)(s_tq + (tl << 2)) =
                *(const float4*)(g_hq + (size_t)q * ND + (tl << 2));
        s_a[tl] = 0.f;
        __syncthreads();

        // initial tq stats (single uncentered pass; one warp per n per half)
        if (wl < 4) {
            const float* tqn = s_tq + wl * DC;
            float s = 0.f, ss = 0.f;
#pragma unroll
            for (int d = lane; d < DC; d += 32) { float x = tqn[d]; s += x; ss += x * x; }
#pragma unroll
            for (int o = 16; o > 0; o >>= 1) {
                s  += __shfl_xor_sync(0xffffffffu, s, o);
                ss += __shfl_xor_sync(0xffffffffu, ss, o);
            }
            if (lane == 0) { s_stat[2 * wl] = s;  s_stat[8 + 2 * wl] = ss; }
            if (lane == 1) { s_stat[2 * wl + 1] = 0.f; s_stat[8 + 2 * wl + 1] = 0.f; }
        }
        __syncthreads();

        // initial p = tanh(-pearson(tm, tq))   [FFMA2]
        {
            const float* tqn = s_tq + n_own * DC;
            u64 ax = 0ull, ay = 0ull;
#pragma unroll 8
            for (int d = 0; d < DC; d += 4) {
                ulonglong2 x = *(const ulonglong2*)(rowp + d);
                ulonglong2 y = *(const ulonglong2*)(tqn + d);
                ax = ffma2(x.x, y.x, ax);
                ay = ffma2(x.y, y.y, ay);
            }
            float x0, x1, y0, y1;
            f2unpack(ax, x0, x1); f2unpack(ay, y0, y1);
            const float dot = (x0 + x1) + (y0 + y1);
            const float S1  = s_stat[2 * n_own] + s_stat[2 * n_own + 1];
            const float ssr = s_stat[8 + 2 * n_own] + s_stat[8 + 2 * n_own + 1];
            const float syy = ssr - S1 * S1 * (1.0f / DC);
            const float num = dot - s_mu[tl] * S1;
            s_p[tl] = tanhf(-num * rsqrtf(s_sxx[tl] * syy + EPSF));
        }
        __syncthreads();

#pragma unroll
        for (int it = 0; it < 3; it++) {
            // softmax over n (per c), coeff = d + p
            if (tl < CC) {
                float a0 = s_a[tl], a1 = s_a[CC + tl], a2 = s_a[2 * CC + tl], a3 = s_a[3 * CC + tl];
                float mx = fmaxf(fmaxf(a0, a1), fmaxf(a2, a3));
                float e0 = expf(a0 - mx), e1 = expf(a1 - mx), e2 = expf(a2 - mx), e3 = expf(a3 - mx);
                float inv = 1.0f / (e0 + e1 + e2 + e3);
                s_co[tl]          = e0 * inv + s_p[tl];
                s_co[CC + tl]     = e1 * inv + s_p[CC + tl];
                s_co[2 * CC + tl] = e2 * inv + s_p[2 * CC + tl];
                s_co[3 * CC + tl] = e3 * inv + s_p[3 * CC + tl];
            }
            __syncthreads();

            // hat_v for BOTH queries (one tm read) + fused ||hv||^2 warp partials
            if (t < 384) {
                const int n = t / 96;
                const int d = (t - n * 96) << 1;
                const float* basep = s_tm + (n * CC) * DPAD + d;
                const float* c0 = co_q0 + n * CC;
                const float* c1 = co_q1 + n * CC;
                u64 A0 = 0ull, A1 = 0ull;
#pragma unroll 8
                for (int c = 0; c < CC; c++) {
                    u64 v = *(const u64*)(basep + c * DPAD);
                    A0 = ffma2(f2dup(c0[c]), v, A0);
                    A1 = ffma2(f2dup(c1[c]), v, A1);
                }
                float ax0, ay0, ax1, ay1;
                f2unpack(A0, ax0, ay0); f2unpack(A1, ax1, ay1);
                *(float2*)(hv_q0 + n * DC + d) = make_float2(ax0, ay0);
                *(float2*)(hv_q1 + n * DC + d) = make_float2(ax1, ay1);
                float sq0 = ax0 * ax0 + ay0 * ay0;
                float sq1 = ax1 * ax1 + ay1 * ay1;
#pragma unroll
                for (int o = 16; o > 0; o >>= 1) {
                    sq0 += __shfl_xor_sync(0xffffffffu, sq0, o);
                    sq1 += __shfl_xor_sync(0xffffffffu, sq1, o);
                }
                if (lane == 0) { st_q0[16 + warp] = sq0; st_q1[16 + warp] = sq1; }
            }
            __syncthreads();

            if (it == 2) {
                // final: out = hv * squash_scale
                for (int idx = tl; idx < ND; idx += 256) {
                    const int n = idx / DC;
                    const float s = s_stat[16 + 3 * n] + s_stat[16 + 3 * n + 1]
                                  + s_stat[16 + 3 * n + 2];
                    const float scale = s / ((1.0f + s) * sqrtf(s + EPSF));
                    out[(size_t)q * ND + idx] = s_hv[idx] * scale;
                }
                break;
            }

            // update: v = hv*scale ; tq = (tq+v)*0.5 ; fused partial tq stats
            {
                const int n = wl >> 1, seg = wl & 1;
                const int off0 = n * DC + seg * 96;
                const float s4 = s_stat[16 + 3 * n] + s_stat[16 + 3 * n + 1]
                               + s_stat[16 + 3 * n + 2];
                const float scale = s4 / ((1.0f + s4) * sqrtf(s4 + EPSF));
                float s = 0.f, ss = 0.f;
#pragma unroll
                for (int k = 0; k < 3; k++) {
                    const int off = off0 + k * 32 + lane;
                    const float v = s_hv[off] * scale;
                    s_hv[off] = v;
                    const float nt = (s_tq[off] + v) * 0.5f;
                    s_tq[off] = nt;
                    s += nt; ss += nt * nt;
                }
#pragma unroll
                for (int o = 16; o > 0; o >>= 1) {
                    s  += __shfl_xor_sync(0xffffffffu, s, o);
                    ss += __shfl_xor_sync(0xffffffffu, ss, o);
                }
                if (lane == 0) { s_stat[wl] = s; s_stat[8 + wl] = ss; }
            }
            __syncthreads();

            // fused: agree = tm.v ; dotq = tm.tq ; a += p*agree ; new p   [FFMA2]
            {
                const float* vv  = s_hv + n_own * DC;
                const float* tqn = s_tq + n_own * DC;
                u64 gx = 0ull, gy = 0ull, hx = 0ull, hy = 0ull;
#pragma unroll 6
                for (int d = 0; d < DC; d += 4) {
                    ulonglong2 x  = *(const ulonglong2*)(rowp + d);
                    ulonglong2 a4 = *(const ulonglong2*)(vv + d);
                    ulonglong2 b4 = *(const ulonglong2*)(tqn + d);
                    gx = ffma2(x.x, a4.x, gx); gy = ffma2(x.y, a4.y, gy);
                    hx = ffma2(x.x, b4.x, hx); hy = ffma2(x.y, b4.y, hy);
                }
                float g0, g1, g2, g3, h0, h1, h2, h3;
                f2unpack(gx, g0, g1); f2unpack(gy, g2, g3);
                f2unpack(hx, h0, h1); f2unpack(hy, h2, h3);
                const float agree = (g0 + g1) + (g2 + g3);
                const float dotq  = (h0 + h1) + (h2 + h3);
                s_a[tl] += s_p[tl] * agree;
                const float S1  = s_stat[2 * n_own] + s_stat[2 * n_own + 1];
                const float ssr = s_stat[8 + 2 * n_own] + s_stat[8 + 2 * n_own + 1];
                const float syy = ssr - S1 * S1 * (1.0f / DC);
                const float num = dotq - s_mu[tl] * S1;
                s_p[tl] = tanhf(-num * rsqrtf(s_sxx[tl] * syy + EPSF));
            }
            __syncthreads();
        }
    }
}

// =============================================================================
// launch
// =============================================================================
extern "C" void kernel_launch(void* const* d_in, const int* in_sizes, int n_in,
                              void* d_out, int out_size)
{
    const float* m = (const float*)d_in[0];   // [64, 768]
    const float* q = (const float*)d_in[1];   // [512, 768]
    const float* W = (const float*)d_in[2];   // [1, 4, 64, 192, 768]
    const float* b = (const float*)d_in[3];   // [1, 4, 64, 192]
    float* out = (float*)d_out;               // [512, 768]
    (void)in_sizes; (void)n_in; (void)out_size;

    const size_t smem_bytes =
        (size_t)(256 * DPAD + 512 + 2 * PQ) * sizeof(float); // ~216 KB
    cudaFuncSetAttribute(routing_kernel,
                         cudaFuncAttributeMaxDynamicSharedMemorySize,
                         (int)smem_bytes);

    gemm_kernel<<<dim3(12, 12), 256>>>(m, q, W, b);
    routing_kernel<<<148, 512, smem_bytes>>>(out);
}

// round 5
// speedup vs baseline: 1.3002x; 1.0031x over previous
#include <cuda_runtime.h>
#include <cstdint>
#include <cstddef>

// Problem constants
#define NC    4      // NUM_CAPS
#define CC    64     // IN_CAPS
#define DC    192    // DIM_CAPS
#define DPAD  196    // padded row stride in smem (float4-stride 49: conflict-free)
#define QQ    512
#define ND    (NC*DC)   // 768
#define IDIM  768
#define EPSF  1e-8f
#define PQ    2336   // per-query block: a(256)+p(256)+co(256)+tq(768)+hv(768)+stat(32)

__device__ float g_hatm[NC*CC*DC];      // [n][c][d]
__device__ float g_hq[QQ*ND];           // [q][n*192+d]

// ---------------- packed fp32x2 helpers (sm_103a FFMA2 pipe) ----------------
typedef unsigned long long u64;
__device__ __forceinline__ void f2unpack(u64 v, float& lo, float& hi) {
    asm("mov.b64 {%0, %1}, %2;" : "=f"(lo), "=f"(hi) : "l"(v));
}
__device__ __forceinline__ u64 f2dup(float a) {
    u64 r;
    asm("mov.b64 %0, {%1, %1};" : "=l"(r) : "f"(a));
    return r;
}
__device__ __forceinline__ u64 ffma2(u64 a, u64 b, u64 c) {
    u64 d;
    asm("fma.rn.f32x2 %0, %1, %2, %3;" : "=l"(d) : "l"(a), "l"(b), "l"(c));
    return d;
}

// =============================================================================
// Kernel 1: fused GEMM  C[576 x 768] = [m;q] @ Wl^T  (FFMA2)
// BM=48, BN=64, KT=64 -> grid (12,12) = 144 CTAs = one full wave.
// Scalar As (pad 68), dup in-register; 3x4 microtile per thread.
// =============================================================================
#define GBM 48
#define GBN 64
#define GKT 64
#define APAD 68

__global__ __launch_bounds__(256, 1)
void gemm_kernel(const float* __restrict__ Am, const float* __restrict__ Aq,
                 const float* __restrict__ W,  const float* __restrict__ Bb)
{
    __shared__ __align__(16) float As[GBM][APAD];      // 48*68*4 = 13056 B
    __shared__ __align__(16) float Bs[GKT][GBN + 4];   // 64*68*4 = 17408 B

    const int t   = threadIdx.x;
    const int tx  = t & 15;
    const int ty  = t >> 4;
    const int row0 = blockIdx.y * GBM;
    const int col0 = blockIdx.x * GBN;

    // A loader: 3 float4 per thread covering the 48x64 tile
    const float* aptr[3];
    int arow[3], acol[3];
#pragma unroll
    for (int j = 0; j < 3; j++) {
        const int i = t + 256 * j;           // 0..767
        arow[j] = i >> 4;                    // 0..47
        acol[j] = (i & 15) << 2;             // 0..60
        const int rg = row0 + arow[j];
        aptr[j] = ((rg < 64) ? (Am + (size_t)rg * IDIM)
                             : (Aq + (size_t)(rg - 64) * IDIM)) + acol[j];
    }

    // B loader: 4 float4 per thread (one W row segment of 64 k)
    const int lb_j = t >> 2;                 // 0..63
    const int lb_k = (t & 3) << 2;           // 0,4,8,12
    const int gj = col0 + lb_j;
    const int bn = gj / DC;
    const int bd = gj - bn * DC;
    const float* brow = W + ((size_t)bn * CC * DC + bd) * IDIM + lb_k;

    u64 acc[3][2];
#pragma unroll
    for (int i = 0; i < 3; i++) { acc[i][0] = 0ull; acc[i][1] = 0ull; }

    for (int kt = 0; kt < IDIM; kt += GKT) {
#pragma unroll
        for (int j = 0; j < 3; j++) {
            float4 a = *(const float4*)(aptr[j] + kt);
            *(float4*)&As[arow[j]][acol[j]] = a;
        }
#pragma unroll
        for (int c = 0; c < 4; c++) {
            float4 b = *(const float4*)(brow + kt + 16 * c);
            Bs[lb_k + 16 * c + 0][lb_j] = b.x;
            Bs[lb_k + 16 * c + 1][lb_j] = b.y;
            Bs[lb_k + 16 * c + 2][lb_j] = b.z;
            Bs[lb_k + 16 * c + 3][lb_j] = b.w;
        }
        __syncthreads();
#pragma unroll 16
        for (int k = 0; k < GKT; k++) {
            ulonglong2 bp = *(const ulonglong2*)&Bs[k][tx << 2];
            u64 a0 = f2dup(As[ty * 3 + 0][k]);
            u64 a1 = f2dup(As[ty * 3 + 1][k]);
            u64 a2 = f2dup(As[ty * 3 + 2][k]);
            acc[0][0] = ffma2(a0, bp.x, acc[0][0]);
            acc[0][1] = ffma2(a0, bp.y, acc[0][1]);
            acc[1][0] = ffma2(a1, bp.x, acc[1][0]);
            acc[1][1] = ffma2(a1, bp.y, acc[1][1]);
            acc[2][0] = ffma2(a2, bp.x, acc[2][0]);
            acc[2][1] = ffma2(a2, bp.y, acc[2][1]);
        }
        __syncthreads();
    }

    const int jb = col0 + (tx << 2);
#pragma unroll
    for (int i = 0; i < 3; i++) {
        const int r = row0 + ty * 3 + i;
        float v0, v1, v2, v3;
        f2unpack(acc[i][0], v0, v1);
        f2unpack(acc[i][1], v2, v3);
        if (r < 64) {
            float vv[4] = {v0, v1, v2, v3};
#pragma unroll
            for (int cj = 0; cj < 4; cj++) {
                const int j = jb + cj;
                const int n = j / DC;
                const int d = j - n * DC;
                const int idx = (n * CC + r) * DC + d;
                g_hatm[idx] = vv[cj] + Bb[idx];
            }
        } else {
            float4 o; o.x = v0; o.y = v1; o.z = v2; o.w = v3;
            *(float4*)(g_hq + (size_t)(r - 64) * ND + jb) = o;
        }
    }
}

// =============================================================================
// Kernel 2: routing, 512 threads = two 256-thread halves (query pair).
// tm resident in smem. FFMA2 dot loops; squash fused into hat_v.
// s_stat per query: [0..7] S1 partials (2/n), [8..15] ss partials,
//                   [16..27] ||hv||^2 warp partials (3/n).
// =============================================================================
__global__ __launch_bounds__(512, 1)
void routing_kernel(float* __restrict__ out)
{
    extern __shared__ float sm[];
    float* s_tm  = sm;                         // [256][196]
    float* s_mu  = sm + 256 * DPAD;            // 256 (query-independent)
    float* s_sxx = s_mu + 256;                 // 256
    float* qbase = s_sxx + 256;                // 2 x PQ

    const int t    = threadIdx.x;
    const int qi   = t >> 8;
    const int tl   = t & 255;
    const int warp = t >> 5;
    const int lane = t & 31;
    const int wl   = warp & 7;
    const int n_own = tl >> 6;

    float* qb     = qbase + qi * PQ;
    float* s_a    = qb;
    float* s_p    = qb + 256;
    float* s_co   = qb + 512;
    float* s_tq   = qb + 768;
    float* s_hv   = qb + 1536;
    float* s_stat = qb + 2304;
    float* co_q0  = qbase + 512;
    float* co_q1  = qbase + PQ + 512;
    float* hv_q0  = qbase + 1536;
    float* hv_q1  = qbase + PQ + 1536;
    float* st_q0  = qbase + 2304;
    float* st_q1  = qbase + PQ + 2304;

    const float* rowp = s_tm + tl * DPAD;

    // Load tm
    for (int idx = t; idx < NC * CC * DC; idx += 512) {
        const int row = idx / DC;
        const int d = idx - row * DC;
        s_tm[row * DPAD + d] = g_hatm[idx];
    }
    __syncthreads();

    // Per-(n,c) tm stats (query-independent)
    if (qi == 0) {
        float s = 0.f;
#pragma unroll 8
        for (int d = 0; d < DC; d += 4) {
            float4 v = *(const float4*)(rowp + d);
            s += (v.x + v.y) + (v.z + v.w);
        }
        const float mu = s * (1.0f / DC);
        float ss = 0.f;
#pragma unroll 8
        for (int d = 0; d < DC; d += 4) {
            float4 v = *(const float4*)(rowp + d);
            float e0 = v.x - mu, e1 = v.y - mu, e2 = v.z - mu, e3 = v.w - mu;
            ss += (e0 * e0 + e1 * e1) + (e2 * e2 + e3 * e3);
        }
        s_mu[tl] = mu; s_sxx[tl] = ss;
    }

    for (int pp = blockIdx.x; pp < QQ / 2; pp += gridDim.x) {
        const int q = 2 * pp + qi;
        __syncthreads();

        if (tl < 192)
            *(float4*)(s_tq + (tl << 2)) =
                *(const float4*)(g_hq + (size_t)q * ND + (tl << 2));
        s_a[tl] = 0.f;
        __syncthreads();

        // initial tq stats (single uncentered pass; one warp per n per half)
        if (wl < 4) {
            const float* tqn = s_tq + wl * DC;
            float s = 0.f, ss = 0.f;
#pragma unroll
            for (int d = lane; d < DC; d += 32) { float x = tqn[d]; s += x; ss += x * x; }
#pragma unroll
            for (int o = 16; o > 0; o >>= 1) {
                s  += __shfl_xor_sync(0xffffffffu, s, o);
                ss += __shfl_xor_sync(0xffffffffu, ss, o);
            }
            if (lane == 0) { s_stat[2 * wl] = s;  s_stat[8 + 2 * wl] = ss; }
            if (lane == 1) { s_stat[2 * wl + 1] = 0.f; s_stat[8 + 2 * wl + 1] = 0.f; }
        }
        __syncthreads();

        // initial p = tanh(-pearson(tm, tq))   [FFMA2]
        {
            const float* tqn = s_tq + n_own * DC;
            u64 ax = 0ull, ay = 0ull;
#pragma unroll 8
            for (int d = 0; d < DC; d += 4) {
                ulonglong2 x = *(const ulonglong2*)(rowp + d);
                ulonglong2 y = *(const ulonglong2*)(tqn + d);
                ax = ffma2(x.x, y.x, ax);
                ay = ffma2(x.y, y.y, ay);
            }
            float x0, x1, y0, y1;
            f2unpack(ax, x0, x1); f2unpack(ay, y0, y1);
            const float dot = (x0 + x1) + (y0 + y1);
            const float S1  = s_stat[2 * n_own] + s_stat[2 * n_own + 1];
            const float ssr = s_stat[8 + 2 * n_own] + s_stat[8 + 2 * n_own + 1];
            const float syy = ssr - S1 * S1 * (1.0f / DC);
            const float num = dot - s_mu[tl] * S1;
            s_p[tl] = tanhf(-num * rsqrtf(s_sxx[tl] * syy + EPSF));
        }
        __syncthreads();

#pragma unroll
        for (int it = 0; it < 3; it++) {
            // softmax over n (per c), coeff = d + p
            if (tl < CC) {
                float a0 = s_a[tl], a1 = s_a[CC + tl], a2 = s_a[2 * CC + tl], a3 = s_a[3 * CC + tl];
                float mx = fmaxf(fmaxf(a0, a1), fmaxf(a2, a3));
                float e0 = expf(a0 - mx), e1 = expf(a1 - mx), e2 = expf(a2 - mx), e3 = expf(a3 - mx);
                float inv = 1.0f / (e0 + e1 + e2 + e3);
                s_co[tl]          = e0 * inv + s_p[tl];
                s_co[CC + tl]     = e1 * inv + s_p[CC + tl];
                s_co[2 * CC + tl] = e2 * inv + s_p[2 * CC + tl];
                s_co[3 * CC + tl] = e3 * inv + s_p[3 * CC + tl];
            }
            __syncthreads();

            // hat_v for BOTH queries (one tm read) + fused ||hv||^2 warp partials
            if (t < 384) {
                const int n = t / 96;
                const int d = (t - n * 96) << 1;
                const float* basep = s_tm + (n * CC) * DPAD + d;
                const float* c0 = co_q0 + n * CC;
                const float* c1 = co_q1 + n * CC;
                u64 A0 = 0ull, A1 = 0ull;
#pragma unroll 8
                for (int c = 0; c < CC; c++) {
                    u64 v = *(const u64*)(basep + c * DPAD);
                    A0 = ffma2(f2dup(c0[c]), v, A0);
                    A1 = ffma2(f2dup(c1[c]), v, A1);
                }
                float ax0, ay0, ax1, ay1;
                f2unpack(A0, ax0, ay0); f2unpack(A1, ax1, ay1);
                *(float2*)(hv_q0 + n * DC + d) = make_float2(ax0, ay0);
                *(float2*)(hv_q1 + n * DC + d) = make_float2(ax1, ay1);
                float sq0 = ax0 * ax0 + ay0 * ay0;
                float sq1 = ax1 * ax1 + ay1 * ay1;
#pragma unroll
                for (int o = 16; o > 0; o >>= 1) {
                    sq0 += __shfl_xor_sync(0xffffffffu, sq0, o);
                    sq1 += __shfl_xor_sync(0xffffffffu, sq1, o);
                }
                if (lane == 0) { st_q0[16 + warp] = sq0; st_q1[16 + warp] = sq1; }
            }
            __syncthreads();

            if (it == 2) {
                // final: out = hv * squash_scale
                for (int idx = tl; idx < ND; idx += 256) {
                    const int n = idx / DC;
                    const float s = s_stat[16 + 3 * n] + s_stat[16 + 3 * n + 1]
                                  + s_stat[16 + 3 * n + 2];
                    const float scale = s / ((1.0f + s) * sqrtf(s + EPSF));
                    out[(size_t)q * ND + idx] = s_hv[idx] * scale;
                }
                break;
            }

            // update: v = hv*scale ; tq = (tq+v)*0.5 ; fused partial tq stats
            {
                const int n = wl >> 1, seg = wl & 1;
                const int off0 = n * DC + seg * 96;
                const float s4 = s_stat[16 + 3 * n] + s_stat[16 + 3 * n + 1]
                               + s_stat[16 + 3 * n + 2];
                const float scale = s4 / ((1.0f + s4) * sqrtf(s4 + EPSF));
                float s = 0.f, ss = 0.f;
#pragma unroll
                for (int k = 0; k < 3; k++) {
                    const int off = off0 + k * 32 + lane;
                    const float v = s_hv[off] * scale;
                    s_hv[off] = v;
                    const float nt = (s_tq[off] + v) * 0.5f;
                    s_tq[off] = nt;
                    s += nt; ss += nt * nt;
                }
#pragma unroll
                for (int o = 16; o > 0; o >>= 1) {
                    s  += __shfl_xor_sync(0xffffffffu, s, o);
                    ss += __shfl_xor_sync(0xffffffffu, ss, o);
                }
                if (lane == 0) { s_stat[wl] = s; s_stat[8 + wl] = ss; }
            }
            __syncthreads();

            // fused: agree = tm.v ; dotq = tm.tq ; a += p*agree ; new p   [FFMA2]
            {
                const float* vv  = s_hv + n_own * DC;
                const float* tqn = s_tq + n_own * DC;
                u64 gx = 0ull, gy = 0ull, hx = 0ull, hy = 0ull;
#pragma unroll 6
                for (int d = 0; d < DC; d += 4) {
                    ulonglong2 x  = *(const ulonglong2*)(rowp + d);
                    ulonglong2 a4 = *(const ulonglong2*)(vv + d);
                    ulonglong2 b4 = *(const ulonglong2*)(tqn + d);
                    gx = ffma2(x.x, a4.x, gx); gy = ffma2(x.y, a4.y, gy);
                    hx = ffma2(x.x, b4.x, hx); hy = ffma2(x.y, b4.y, hy);
                }
                float g0, g1, g2, g3, h0, h1, h2, h3;
                f2unpack(gx, g0, g1); f2unpack(gy, g2, g3);
                f2unpack(hx, h0, h1); f2unpack(hy, h2, h3);
                const float agree = (g0 + g1) + (g2 + g3);
                const float dotq  = (h0 + h1) + (h2 + h3);
                s_a[tl] += s_p[tl] * agree;
                const float S1  = s_stat[2 * n_own] + s_stat[2 * n_own + 1];
                const float ssr = s_stat[8 + 2 * n_own] + s_stat[8 + 2 * n_own + 1];
                const float syy = ssr - S1 * S1 * (1.0f / DC);
                const float num = dotq - s_mu[tl] * S1;
                s_p[tl] = tanhf(-num * rsqrtf(s_sxx[tl] * syy + EPSF));
            }
            __syncthreads();
        }
    }
}

// =============================================================================
// launch
// =============================================================================
extern "C" void kernel_launch(void* const* d_in, const int* in_sizes, int n_in,
                              void* d_out, int out_size)
{
    const float* m = (const float*)d_in[0];   // [64, 768]
    const float* q = (const float*)d_in[1];   // [512, 768]
    const float* W = (const float*)d_in[2];   // [1, 4, 64, 192, 768]
    const float* b = (const float*)d_in[3];   // [1, 4, 64, 192]
    float* out = (float*)d_out;               // [512, 768]
    (void)in_sizes; (void)n_in; (void)out_size;

    const size_t smem_bytes =
        (size_t)(256 * DPAD + 512 + 2 * PQ) * sizeof(float); // ~216 KB
    cudaFuncSetAttribute(routing_kernel,
                         cudaFuncAttributeMaxDynamicSharedMemorySize,
                         (int)smem_bytes);

    gemm_kernel<<<dim3(12, 12), 256>>>(m, q, W, b);
    routing_kernel<<<148, 512, smem_bytes>>>(out);
}